// round 10
// baseline (speedup 1.0000x reference)
#include <cuda_runtime.h>
#include <cstddef>

#define ALPHA_ 0.0001f
#define NN 16
#define TT 8
#define VV 256
#define FF 64
#define NVV (NN*VV*VV)
#define YS 68               // padded row stride: 272B, conflict-free patterns
#define NBLK 128

__device__ float g_sloss[NBLK];
__device__ float g_dloss[NN];
__device__ unsigned int g_counter = 0;

// grid (8 j-tiles, 16 n), 512 threads = 16 warps.
// Warp w: i-band (w>>1)*32, j-half (w&1)*16. Lane: li=lane&7, lj=lane>>3.
// Thread tile: 4 i (iband+li+8k) x 4 j (jh+4m+lj) -> 16 scalar accumulators.
// Max-trick: sum_f|yi-yj| = 2*sum_f max(yi,yj) - Ti - Tj (T = row sums).
// Inner loop: 1 FMNMX (alu) + 1 FADD (fma) per element; loads amortized 4x
// by the register tile -> 2048 LDS.128/block (half of R9's crossbar load).
extern "C" __global__ void __launch_bounds__(512, 1)
fused_kernel(const float* __restrict__ x, const float* __restrict__ a,
             float* __restrict__ out) {
    extern __shared__ float y[];            // [256][YS] y = xm*a (~68KB)
    __shared__ float red[512];
    __shared__ float Ts[VV];
    __shared__ float part[16][32];
    __shared__ float cs[32];
    __shared__ float sqw[16];
    __shared__ float wsum[16];

    const int tid  = threadIdx.x;
    const int lane = tid & 31;
    const int w    = tid >> 5;
    const int li   = lane & 7;
    const int lj   = lane >> 3;
    const int n    = blockIdx.y;
    const int jt   = blockIdx.x;
    const float* __restrict__ xm = x + (size_t)(n * TT + TT / 2) * (VV * FF);

    // Stage y = xm * a (tid&63 = fixed feature -> free per-f raw sums).
    const int   f  = tid & 63;
    const float af = __ldg(&a[f]);
    float Sx = 0.f, Sq = 0.f;
#pragma unroll
    for (int k = 0; k < 32; ++k) {
        int idx = tid + (k << 9);
        float v = xm[idx];
        y[(idx >> 6) * YS + f] = v * af;
        Sx += v;
        Sq = fmaf(v, v, Sq);
    }
    red[tid] = Sx;
#pragma unroll
    for (int o = 16; o; o >>= 1) Sq += __shfl_down_sync(~0u, Sq, o);
    if (lane == 0) sqw[w] = Sq;
    __syncthreads();

    // Row sums T_r (one-time).
    if (tid < VV) {
        const float4* p = reinterpret_cast<const float4*>(&y[tid * YS]);
        float s0 = 0.f, s1 = 0.f, s2 = 0.f, s3 = 0.f;
#pragma unroll
        for (int k = 0; k < 16; k += 4) {
            float4 v0 = p[k], v1 = p[k + 1], v2 = p[k + 2], v3 = p[k + 3];
            s0 += v0.x + v0.y + v0.z + v0.w;
            s1 += v1.x + v1.y + v1.z + v1.w;
            s2 += v2.x + v2.y + v2.z + v2.w;
            s3 += v3.x + v3.y + v3.z + v3.w;
        }
        Ts[tid] = (s0 + s1) + (s2 + s3);
    }

    // dloss_n = 2*(V*sum x^2 - sum_f (sum_i x)^2); valid because S's column
    // sums are exactly 1 (softmax axis) so sum(S@d2) == sum(d2).
    if (jt == 0 && w == 1) {
        float s1 = 0.f, s2 = 0.f;
#pragma unroll
        for (int r = 0; r < 8; ++r) {
            s1 += red[lane + (r << 6)];
            s2 += red[lane + 32 + (r << 6)];
        }
        float t  = s1 * s1 + s2 * s2;
        float sq = (lane < 16) ? sqw[lane] : 0.f;
#pragma unroll
        for (int o = 16; o; o >>= 1) {
            t  += __shfl_down_sync(~0u, t, o);
            sq += __shfl_down_sync(~0u, sq, o);
        }
        if (lane == 0) __stcg(&g_dloss[n], 2.f * ((float)VV * sq - t));
    }
    __syncthreads();

    const int iband = (w >> 1) * 32;
    const int jh    = (w & 1) * 16;
    const float* __restrict__ xib = y + (iband + li) * YS;           // +8k*YS
    const float* __restrict__ xjb = y + (jt * 32 + jh + lj) * YS;    // +4m*YS

    float acc[16];
#pragma unroll
    for (int p = 0; p < 16; ++p) acc[p] = 0.f;

#pragma unroll 4
    for (int h = 0; h < 16; ++h) {
        float4 xi[4], xj[4];
#pragma unroll
        for (int k = 0; k < 4; ++k)   // 8 li-consecutive rows: full bank cycle
            xi[k] = *reinterpret_cast<const float4*>(xib + k * 8 * YS + h * 4);
#pragma unroll
        for (int m = 0; m < 4; ++m)   // 4 lj-consecutive rows: banks 0/16/32/48
            xj[m] = *reinterpret_cast<const float4*>(xjb + m * 4 * YS + h * 4);
#pragma unroll
        for (int k = 0; k < 4; ++k)
#pragma unroll
            for (int m = 0; m < 4; ++m) {
                float s = acc[k * 4 + m];
                s += fmaxf(xi[k].x, xj[m].x);    // FMNMX (alu) + FADD (fma)
                s += fmaxf(xi[k].y, xj[m].y);
                s += fmaxf(xi[k].z, xj[m].z);
                s += fmaxf(xi[k].w, xj[m].w);
                acc[k * 4 + m] = s;
            }
    }

    // score = 2*acc - Ti - Tj (>= 0: relu is identity); exp + col partials.
    float Ti[4], Tj[4];
#pragma unroll
    for (int k = 0; k < 4; ++k) Ti[k] = Ts[iband + li + 8 * k];
#pragma unroll
    for (int m = 0; m < 4; ++m) Tj[m] = Ts[jt * 32 + jh + 4 * m + lj];

    float e[16];
    float cp[4] = {0.f, 0.f, 0.f, 0.f};
#pragma unroll
    for (int k = 0; k < 4; ++k)
#pragma unroll
        for (int m = 0; m < 4; ++m) {
            float v = __expf(2.f * acc[k * 4 + m] - Ti[k] - Tj[m]);
            e[k * 4 + m] = v;
            cp[m] += v;
        }
    // Reduce cp over li (8-lane groups share the same j-set).
#pragma unroll
    for (int o = 4; o; o >>= 1)
#pragma unroll
        for (int m = 0; m < 4; ++m) cp[m] += __shfl_down_sync(~0u, cp[m], o);
    if (li == 0)
#pragma unroll
        for (int m = 0; m < 4; ++m) part[w][jh + 4 * m + lj] = cp[m];
    __syncthreads();
    if (tid < 32) {
        const int o = (tid >> 4) & 1;        // which jh owns this column
        float s = 0.f;
#pragma unroll
        for (int p = 0; p < 8; ++p) s += part[2 * p + o][tid];
        cs[tid] = 1.0f / s;
    }
    __syncthreads();

    float iv[4];
#pragma unroll
    for (int m = 0; m < 4; ++m) iv[m] = cs[jh + 4 * m + lj];

    // Normalize, write S, accumulate S^2.
    float sq2 = 0.f;
    float* ob = out + (size_t)n * (VV * VV) + jt * 32 + jh + lj;
#pragma unroll
    for (int k = 0; k < 4; ++k) {
        const size_t ro = (size_t)(iband + li + 8 * k) * VV;
#pragma unroll
        for (int m = 0; m < 4; ++m) {
            float Sv = e[k * 4 + m] * iv[m];
            ob[ro + 4 * m] = Sv;
            sq2 = fmaf(Sv, Sv, sq2);
        }
    }
#pragma unroll
    for (int o = 16; o; o >>= 1) sq2 += __shfl_down_sync(~0u, sq2, o);
    if (lane == 0) wsum[w] = sq2;
    __syncthreads();

    // Last-block finalize (graph-safe: counter reset each call).
    __shared__ unsigned int s_flag;
    const int bid = n * 8 + jt;
    if (tid == 0) {
        float t = 0.f;
#pragma unroll
        for (int k = 0; k < 16; ++k) t += wsum[k];
        __stcg(&g_sloss[bid], t);
        __threadfence();
        unsigned int c = atomicAdd(&g_counter, 1u);
        s_flag = (c == NBLK - 1) ? 1u : 0u;
    }
    __syncthreads();
    if (s_flag && w == 0) {
        __threadfence();
        float s = 0.f;
#pragma unroll
        for (int k = 0; k < 4; ++k) s += __ldcg(&g_sloss[lane + (k << 5)]);
        float dl = (lane < NN) ? __ldcg(&g_dloss[lane]) : 0.f;
#pragma unroll
        for (int o = 16; o; o >>= 1) {
            s  += __shfl_down_sync(~0u, s, o);
            dl += __shfl_down_sync(~0u, dl, o);
        }
        if (lane == 0) {
            out[NVV]     = s * (ALPHA_ / (float)NN);
            out[NVV + 1] = dl * ALPHA_;
            g_counter = 0;
        }
    }
}

extern "C" void kernel_launch(void* const* d_in, const int* in_sizes, int n_in,
                              void* d_out, int out_size) {
    const float* x = (const float*)d_in[0];
    const float* a = (const float*)d_in[1];
    if (n_in >= 2 && in_sizes[0] == FF) {      // defensive input-order check
        const float* t = x; x = a; a = t;
    }
    float* out = (float*)d_out;

    const int smem = VV * YS * (int)sizeof(float);
    cudaFuncSetAttribute(fused_kernel,
                         cudaFuncAttributeMaxDynamicSharedMemorySize, smem);
    fused_kernel<<<dim3(8, NN), 512, smem>>>(x, a, out);
}

// round 11
// speedup vs baseline: 1.0019x; 1.0019x over previous
#include <cuda_runtime.h>
#include <cstddef>

#define ALPHA_ 0.0001f
#define NN 16
#define TT 8
#define VV 256
#define FF 64
#define NVV (NN*VV*VV)
#define YS 68               // padded row stride: 272B, conflict-free patterns
#define NBLK 128

__device__ float g_sloss[NBLK];
__device__ float g_dloss[NN];
__device__ unsigned int g_counter = 0;

// grid (8 j-tiles, 16 n), 512 threads = 16 warps.
// Warp w: i-band (w>>1)*32, j-half (w&1)*16. Lane: li=lane&7, lj=lane>>3.
// Thread tile: 4 i (iband+li+8k) x 4 j (jh+4m+lj) -> 16 scalar accumulators.
// Max-trick: sum_f|yi-yj| = 2*sum_f max(yi,yj) - Ti - Tj (T = row sums).
// Main loop SOFTWARE-PIPELINED: h+1's 8 LDS.128 prefetched into registers
// while h's 128 math ops run -> LDS latency overlapped, not serialized.
extern "C" __global__ void __launch_bounds__(512, 1)
fused_kernel(const float* __restrict__ x, const float* __restrict__ a,
             float* __restrict__ out) {
    extern __shared__ float y[];            // [256][YS] y = xm*a (~68KB)
    __shared__ float red[512];
    __shared__ float Ts[VV];
    __shared__ float part[16][32];
    __shared__ float cs[32];
    __shared__ float sqw[16];
    __shared__ float wsum[16];

    const int tid  = threadIdx.x;
    const int lane = tid & 31;
    const int w    = tid >> 5;
    const int li   = lane & 7;
    const int lj   = lane >> 3;
    const int n    = blockIdx.y;
    const int jt   = blockIdx.x;
    const float* __restrict__ xm = x + (size_t)(n * TT + TT / 2) * (VV * FF);

    // Stage y = xm * a (tid&63 = fixed feature -> free per-f raw sums).
    const int   f  = tid & 63;
    const float af = __ldg(&a[f]);
    float Sx = 0.f, Sq = 0.f;
#pragma unroll
    for (int k = 0; k < 32; ++k) {
        int idx = tid + (k << 9);
        float v = xm[idx];
        y[(idx >> 6) * YS + f] = v * af;
        Sx += v;
        Sq = fmaf(v, v, Sq);
    }
    red[tid] = Sx;
#pragma unroll
    for (int o = 16; o; o >>= 1) Sq += __shfl_down_sync(~0u, Sq, o);
    if (lane == 0) sqw[w] = Sq;
    __syncthreads();

    // Row sums T_r (one-time).
    if (tid < VV) {
        const float4* p = reinterpret_cast<const float4*>(&y[tid * YS]);
        float s0 = 0.f, s1 = 0.f, s2 = 0.f, s3 = 0.f;
#pragma unroll
        for (int k = 0; k < 16; k += 4) {
            float4 v0 = p[k], v1 = p[k + 1], v2 = p[k + 2], v3 = p[k + 3];
            s0 += v0.x + v0.y + v0.z + v0.w;
            s1 += v1.x + v1.y + v1.z + v1.w;
            s2 += v2.x + v2.y + v2.z + v2.w;
            s3 += v3.x + v3.y + v3.z + v3.w;
        }
        Ts[tid] = (s0 + s1) + (s2 + s3);
    }

    // dloss_n = 2*(V*sum x^2 - sum_f (sum_i x)^2); valid because S's column
    // sums are exactly 1 (softmax axis) so sum(S@d2) == sum(d2).
    if (jt == 0 && w == 1) {
        float s1 = 0.f, s2 = 0.f;
#pragma unroll
        for (int r = 0; r < 8; ++r) {
            s1 += red[lane + (r << 6)];
            s2 += red[lane + 32 + (r << 6)];
        }
        float t  = s1 * s1 + s2 * s2;
        float sq = (lane < 16) ? sqw[lane] : 0.f;
#pragma unroll
        for (int o = 16; o; o >>= 1) {
            t  += __shfl_down_sync(~0u, t, o);
            sq += __shfl_down_sync(~0u, sq, o);
        }
        if (lane == 0) __stcg(&g_dloss[n], 2.f * ((float)VV * sq - t));
    }
    __syncthreads();

    const int iband = (w >> 1) * 32;
    const int jh    = (w & 1) * 16;
    const float* xp_i = y + (iband + li) * YS;           // + k*8*YS (+4/iter)
    const float* xp_j = y + (jt * 32 + jh + lj) * YS;    // + m*4*YS (+4/iter)

    float acc[16];
#pragma unroll
    for (int p = 0; p < 16; ++p) acc[p] = 0.f;

    // Pipelined main loop: prefetch h+1 while computing h.
    float4 cxi[4], cxj[4];
#pragma unroll
    for (int k = 0; k < 4; ++k)
        cxi[k] = *reinterpret_cast<const float4*>(xp_i + k * 8 * YS);
#pragma unroll
    for (int m = 0; m < 4; ++m)
        cxj[m] = *reinterpret_cast<const float4*>(xp_j + m * 4 * YS);

#pragma unroll 4
    for (int h = 0; h < 16; ++h) {
        float4 nxi[4], nxj[4];
#pragma unroll
        for (int k = 0; k < 4; ++k)   // prefetch next chunk (h=15 reads row
            nxi[k] = *reinterpret_cast<const float4*>(xp_i + k * 8 * YS + 4);
#pragma unroll
        for (int m = 0; m < 4; ++m)   // padding: in-bounds, values unused)
            nxj[m] = *reinterpret_cast<const float4*>(xp_j + m * 4 * YS + 4);

#pragma unroll
        for (int k = 0; k < 4; ++k)
#pragma unroll
            for (int m = 0; m < 4; ++m) {
                float s = acc[k * 4 + m];
                s += fmaxf(cxi[k].x, cxj[m].x);   // FMNMX (alu) + FADD (fma)
                s += fmaxf(cxi[k].y, cxj[m].y);
                s += fmaxf(cxi[k].z, cxj[m].z);
                s += fmaxf(cxi[k].w, cxj[m].w);
                acc[k * 4 + m] = s;
            }
#pragma unroll
        for (int k = 0; k < 4; ++k) cxi[k] = nxi[k];
#pragma unroll
        for (int m = 0; m < 4; ++m) cxj[m] = nxj[m];
        xp_i += 4;
        xp_j += 4;
    }

    // score = 2*acc - Ti - Tj (>= 0: relu is identity); exp + col partials.
    float Ti[4], Tj[4];
#pragma unroll
    for (int k = 0; k < 4; ++k) Ti[k] = Ts[iband + li + 8 * k];
#pragma unroll
    for (int m = 0; m < 4; ++m) Tj[m] = Ts[jt * 32 + jh + 4 * m + lj];

    float e[16];
    float cp[4] = {0.f, 0.f, 0.f, 0.f};
#pragma unroll
    for (int k = 0; k < 4; ++k)
#pragma unroll
        for (int m = 0; m < 4; ++m) {
            float v = __expf(2.f * acc[k * 4 + m] - Ti[k] - Tj[m]);
            e[k * 4 + m] = v;
            cp[m] += v;
        }
    // Reduce cp over li (8-lane groups share the same j-set).
#pragma unroll
    for (int o = 4; o; o >>= 1)
#pragma unroll
        for (int m = 0; m < 4; ++m) cp[m] += __shfl_down_sync(~0u, cp[m], o);
    if (li == 0)
#pragma unroll
        for (int m = 0; m < 4; ++m) part[w][jh + 4 * m + lj] = cp[m];
    __syncthreads();
    if (tid < 32) {
        const int o = (tid >> 4) & 1;        // which jh owns this column
        float s = 0.f;
#pragma unroll
        for (int p = 0; p < 8; ++p) s += part[2 * p + o][tid];
        cs[tid] = 1.0f / s;
    }
    __syncthreads();

    float iv[4];
#pragma unroll
    for (int m = 0; m < 4; ++m) iv[m] = cs[jh + 4 * m + lj];

    // Normalize, write S, accumulate S^2.
    float sq2 = 0.f;
    float* ob = out + (size_t)n * (VV * VV) + jt * 32 + jh + lj;
#pragma unroll
    for (int k = 0; k < 4; ++k) {
        const size_t ro = (size_t)(iband + li + 8 * k) * VV;
#pragma unroll
        for (int m = 0; m < 4; ++m) {
            float Sv = e[k * 4 + m] * iv[m];
            ob[ro + 4 * m] = Sv;
            sq2 = fmaf(Sv, Sv, sq2);
        }
    }
#pragma unroll
    for (int o = 16; o; o >>= 1) sq2 += __shfl_down_sync(~0u, sq2, o);
    if (lane == 0) wsum[w] = sq2;
    __syncthreads();

    // Last-block finalize (graph-safe: counter reset each call).
    __shared__ unsigned int s_flag;
    const int bid = n * 8 + jt;
    if (tid == 0) {
        float t = 0.f;
#pragma unroll
        for (int k = 0; k < 16; ++k) t += wsum[k];
        __stcg(&g_sloss[bid], t);
        __threadfence();
        unsigned int c = atomicAdd(&g_counter, 1u);
        s_flag = (c == NBLK - 1) ? 1u : 0u;
    }
    __syncthreads();
    if (s_flag && w == 0) {
        __threadfence();
        float s = 0.f;
#pragma unroll
        for (int k = 0; k < 4; ++k) s += __ldcg(&g_sloss[lane + (k << 5)]);
        float dl = (lane < NN) ? __ldcg(&g_dloss[lane]) : 0.f;
#pragma unroll
        for (int o = 16; o; o >>= 1) {
            s  += __shfl_down_sync(~0u, s, o);
            dl += __shfl_down_sync(~0u, dl, o);
        }
        if (lane == 0) {
            out[NVV]     = s * (ALPHA_ / (float)NN);
            out[NVV + 1] = dl * ALPHA_;
            g_counter = 0;
        }
    }
}

extern "C" void kernel_launch(void* const* d_in, const int* in_sizes, int n_in,
                              void* d_out, int out_size) {
    const float* x = (const float*)d_in[0];
    const float* a = (const float*)d_in[1];
    if (n_in >= 2 && in_sizes[0] == FF) {      // defensive input-order check
        const float* t = x; x = a; a = t;
    }
    float* out = (float*)d_out;

    const int smem = VV * YS * (int)sizeof(float);
    cudaFuncSetAttribute(fused_kernel,
                         cudaFuncAttributeMaxDynamicSharedMemorySize, smem);
    fused_kernel<<<dim3(8, NN), 512, smem>>>(x, a, out);
}